// round 8
// baseline (speedup 1.0000x reference)
#include <cuda_runtime.h>

// Problem constants
#define BATCH 2
#define DD 160
#define HH 160
#define WW 160
#define PLANE (HH * WW)               // 25600
#define NVOX (BATCH * DD * HH * WW)   // 8,192,000
#define NCH 5
#define RAD 4
#define INV_WIN (1.0f / 729.0f)

// ---- Kernel 1 (fused W+H) tiling ----
#define TH 16                          // output rows per block
#define NR (TH + 2 * RAD)              // 24 staged rows
#define NTH1 640                       // threads per block
#define HT (HH / TH)                   // 10 h-tiles
#define GRID1 (BATCH * DD * HT)        // 3200 blocks
// static smem: 3 * NR * WW * 4 = 46,080 bytes  (<48KB, no opt-in needed)

// ---- Kernel 2 (D + cc) ----
#define W4 (WW / 4)                    // 40 float4 per row
#define PLANE4 (HH * W4)               // 6400
#define NVOX4 (NVOX / 4)
#define CDCHUNK 32
#define NCHUNK (DD / CDCHUNK)          // 5
#define HB 4                           // h rows per block
#define NTH2 (W4 * HB)                 // 160 threads
#define GRID2 (NCHUNK * BATCH * (HH / HB))  // 400 blocks

// Scratch (allocation-free: __device__ globals)
__device__ float g_buf[(size_t)NCH * NVOX];   // W+H summed, 5 channels
__device__ float g_partial[GRID2];

// ---------------------------------------------------------------------------
// Kernel 1: fused products + W-sum + H-sum, one channel at a time through a
// single reused smem scratch buffer (keeps static smem under 48 KB).
// Block handles TH output rows of one (b,d) plane.
// ---------------------------------------------------------------------------
__global__ void __launch_bounds__(NTH1) pass_wh_kernel(const float* __restrict__ I,
                                                       const float* __restrict__ J) {
    __shared__ float s_I[NR * WW];
    __shared__ float s_J[NR * WW];
    __shared__ float s_W[NR * WW];

    const int tid = threadIdx.x;
    const int bd = blockIdx.x / HT;    // plane index b*DD + d
    const int ht = blockIdx.x % HT;
    const int h0 = ht * TH;
    const size_t pbase = (size_t)bd * PLANE;

    // --- Stage 0: load NR raw rows of I and J (zero-fill out-of-range h) ---
    #pragma unroll
    for (int k = 0; k < (NR * WW) / NTH1; k++) {
        const int pos = k * NTH1 + tid;          // coalesced
        const int r = pos / WW;
        const int x = pos % WW;
        const int h = h0 - RAD + r;
        float iv = 0.f, jv = 0.f;
        if (h >= 0 && h < HH) {
            iv = I[pbase + (size_t)h * WW + x];
            jv = J[pbase + (size_t)h * WW + x];
        }
        s_I[r * WW + x] = iv;
        s_J[r * WW + x] = jv;
    }
    __syncthreads();

    const int w = tid % WW;            // for stage 2
    const int g = tid / WW;            // 0..3, row group for stage 2
    const int o0 = g * 4;

    // --- Per-channel: W-sum into s_W, then H-sum streamed to g_buf[c] ---
    #pragma unroll
    for (int c = 0; c < NCH; c++) {
        // Stage 1: W-sums, per-thread sliding windows.
        // 480 active threads: r = t/20, seg = t%20, 8 outputs each.
        if (tid < NR * 20) {
            const int r = tid / 20;
            const int x0 = (tid % 20) * 8;
            const float* rI = s_I + r * WW;
            const float* rJ = s_J + r * WW;
            float acc = 0.f;

            #define PRODUCT(fi, fj) \
                ((c == 0) ? (fi) : (c == 1) ? (fj) : (c == 2) ? (fi) * (fi) \
                 : (c == 3) ? (fj) * (fj) : (fi) * (fj))

            #pragma unroll
            for (int xi = x0 - RAD; xi <= x0 + RAD; xi++) {
                if (xi >= 0 && xi < WW) {
                    const float fi = rI[xi], fj = rJ[xi];
                    acc += PRODUCT(fi, fj);
                }
            }
            s_W[r * WW + x0] = acc;
            #pragma unroll
            for (int j = 1; j < 8; j++) {
                const int xa = x0 + j + RAD;
                const int xs = x0 + j - RAD - 1;
                if (xa < WW) {
                    const float fi = rI[xa], fj = rJ[xa];
                    acc += PRODUCT(fi, fj);
                }
                if (xs >= 0) {
                    const float fi = rI[xs], fj = rJ[xs];
                    acc -= PRODUCT(fi, fj);
                }
                s_W[r * WW + x0 + j] = acc;
            }
            #undef PRODUCT
        }
        __syncthreads();

        // Stage 2: H-sums via per-thread running windows, write to g_buf[c].
        // thread: column w, group g handles output rows o0..o0+3.
        {
            const float* wc = s_W + w;
            float* oc = g_buf + (size_t)c * NVOX + pbase + (size_t)(h0 + o0) * WW + w;
            float s = 0.f;
            #pragma unroll
            for (int r = o0; r <= o0 + 2 * RAD; r++) s += wc[r * WW];
            oc[0] = s;
            #pragma unroll
            for (int j = 1; j < 4; j++) {
                s += wc[(o0 + j + 2 * RAD) * WW];
                s -= wc[(o0 + j - 1) * WW];
                oc[(size_t)j * WW] = s;
            }
        }
        if (c != NCH - 1) __syncthreads();   // protect s_W before next channel
    }
}

// ---------------------------------------------------------------------------
// Kernel 2: sliding-sum along D (float4) + fused NCC + block reduction.
// ---------------------------------------------------------------------------
__global__ void __launch_bounds__(NTH2) pass_d_kernel() {
    const int tid = threadIdx.x;
    const int w4 = tid % W4;
    const int hs = tid / W4;           // 0..3
    const int bx = blockIdx.x;
    const int chunk = bx / (BATCH * (HH / HB));
    const int rem = bx % (BATCH * (HH / HB));
    const int b = rem / (HH / HB);
    const int ht = rem % (HH / HB);
    const int h = ht * HB + hs;
    const int d0 = chunk * CDCHUNK;

    const float4* __restrict__ in = (const float4*)g_buf;
    const size_t base = (size_t)b * DD * PLANE4 + (size_t)h * W4 + w4;

    float4 s[NCH];
    #pragma unroll
    for (int c = 0; c < NCH; c++) {
        float4 a = make_float4(0.f, 0.f, 0.f, 0.f);
        #pragma unroll
        for (int dd = d0 - RAD; dd <= d0 + RAD; dd++) {
            if (dd >= 0 && dd < DD) {
                const float4 v = in[(size_t)c * NVOX4 + base + (size_t)dd * PLANE4];
                a.x += v.x; a.y += v.y; a.z += v.z; a.w += v.w;
            }
        }
        s[c] = a;
    }

    float4 cc4 = make_float4(0.f, 0.f, 0.f, 0.f);
    for (int d = d0; d < d0 + CDCHUNK; d++) {
        #define CC_LANE(L)                                                        \
        {                                                                         \
            const float Is = s[0].L, Js = s[1].L, I2 = s[2].L,                    \
                        J2 = s[3].L, IJ = s[4].L;                                 \
            const float cross = IJ - Is * Js * INV_WIN;                           \
            const float Iv = I2 - Is * Is * INV_WIN;                              \
            const float Jv = J2 - Js * Js * INV_WIN;                              \
            cc4.L += (cross * cross) / (Iv * Jv + 1e-5f);                         \
        }
        CC_LANE(x) CC_LANE(y) CC_LANE(z) CC_LANE(w)
        #undef CC_LANE

        if (d != d0 + CDCHUNK - 1) {
            const int add = d + 1 + RAD;
            const int sub = d - RAD;
            #pragma unroll
            for (int c = 0; c < NCH; c++) {
                if (add < DD) {
                    const float4 v = in[(size_t)c * NVOX4 + base + (size_t)add * PLANE4];
                    s[c].x += v.x; s[c].y += v.y; s[c].z += v.z; s[c].w += v.w;
                }
                if (sub >= 0) {
                    const float4 v = in[(size_t)c * NVOX4 + base + (size_t)sub * PLANE4];
                    s[c].x -= v.x; s[c].y -= v.y; s[c].z -= v.z; s[c].w -= v.w;
                }
            }
        }
    }

    float cc_sum = ((cc4.x + cc4.y) + (cc4.z + cc4.w));

    // deterministic reduction: warp shuffle (fixed order), then warp sums
    #pragma unroll
    for (int off = 16; off > 0; off >>= 1)
        cc_sum += __shfl_down_sync(0xFFFFFFFFu, cc_sum, off);

    __shared__ float warp_sums[NTH2 / 32];
    const int lane = tid & 31, warp = tid >> 5;
    if (lane == 0) warp_sums[warp] = cc_sum;
    __syncthreads();
    if (tid == 0) {
        float t = 0.f;
        #pragma unroll
        for (int i = 0; i < NTH2 / 32; i++) t += warp_sums[i];
        g_partial[blockIdx.x] = t;
    }
}

// ---------------------------------------------------------------------------
// Final deterministic reduction of block partials -> scalar out
// ---------------------------------------------------------------------------
__global__ void finalize_kernel(float* __restrict__ out) {
    __shared__ float red[256];
    float a = 0.f;
    for (int i = threadIdx.x; i < GRID2; i += 256) a += g_partial[i];
    red[threadIdx.x] = a;
    __syncthreads();
    #pragma unroll
    for (int off = 128; off > 0; off >>= 1) {
        if (threadIdx.x < off) red[threadIdx.x] += red[threadIdx.x + off];
        __syncthreads();
    }
    if (threadIdx.x == 0) out[0] = -red[0] / (float)NVOX;
}

// ---------------------------------------------------------------------------
extern "C" void kernel_launch(void* const* d_in, const int* in_sizes, int n_in,
                              void* d_out, int out_size) {
    const float* y_true = (const float*)d_in[0];
    const float* y_pred = (const float*)d_in[1];
    float* out = (float*)d_out;

    pass_wh_kernel<<<GRID1, NTH1>>>(y_true, y_pred);
    pass_d_kernel<<<GRID2, NTH2>>>();
    finalize_kernel<<<1, 256>>>(out);
}

// round 12
// speedup vs baseline: 1.8780x; 1.8780x over previous
#include <cuda_runtime.h>

// Problem constants
#define BATCH 2
#define DD 160
#define HH 160
#define WW 160
#define PLANE (HH * WW)               // 25600
#define NVOX (BATCH * DD * HH * WW)   // 8,192,000
#define NCH 5
#define RAD 4
#define INV_WIN (1.0f / 729.0f)

// ---- Kernel 1 (fused W+H, shuffle stencil, zero smem) ----
#define TEAMW 7                        // warps per row: 7*24 = 168 >= 160 outputs
#define NTH1 (TEAMW * 32)              // 224 threads
#define HCH 40                         // h rows per block
#define NCHH (HH / HCH)                // 4
#define GRID1 (BATCH * DD * NCHH)      // 1280 blocks

// ---- Kernel 2 (D + cc) ----
#define W4 (WW / 4)                    // 40 float4 per row
#define PLANE4 (HH * W4)               // 6400
#define NVOX4 (NVOX / 4)
#define CDCHUNK 16
#define NCHUNK (DD / CDCHUNK)          // 10
#define HB 8                           // h rows per block
#define NTH2 (W4 * HB)                 // 320 threads
#define GRID2 (NCHUNK * BATCH * (HH / HB))  // 400 blocks

// Scratch (allocation-free: __device__ globals)
__device__ float g_buf[(size_t)NCH * NVOX];   // W+H summed, 5 channels
__device__ float g_partial[GRID2];

// ---------------------------------------------------------------------------
// Kernel 1: fused products + H-running-window (registers) + W-sum (shuffles).
// No shared memory, no __syncthreads. Each warp: 32 lanes load w = w0+lane-4,
// lanes 4..27 emit outputs w0..w0+23. H window slides via predicated global
// adds/subs (sub taps re-read rows touched 9 steps earlier -> L1/L2 hits).
// ---------------------------------------------------------------------------
__global__ void __launch_bounds__(NTH1) pass_wh_kernel(const float* __restrict__ I,
                                                       const float* __restrict__ J) {
    const int tid = threadIdx.x;
    const int warp = tid >> 5;
    const int lane = tid & 31;

    const int bx = blockIdx.x;
    const int plane = bx / NCHH;       // b*DD + d
    const int hc = bx % NCHH;
    const int h0 = hc * HCH;

    const int w = warp * 24 + lane - 4;            // load column (may be OOB)
    const bool wvalid = (w >= 0 && w < WW);
    const int wc = min(max(w, 0), WW - 1);         // safe address
    const size_t pbase = (size_t)plane * PLANE;
    const float* __restrict__ Ip = I + pbase + wc;
    const float* __restrict__ Jp = J + pbase + wc;

    const int wout = w;                            // output column for lanes 4..27
    const bool emit = (lane >= 4) && (lane < 28) && (wout < WW);

    // H running sums of the 5 products
    float S0 = 0.f, S1 = 0.f, S2 = 0.f, S3 = 0.f, S4 = 0.f;

    // init window for output h0: rows [h0-4, h0+4] (h0+4 <= 124 < HH always)
    #pragma unroll
    for (int k = -RAD; k <= RAD; k++) {
        const int hh = h0 + k;
        if (hh >= 0) {
            const float iv = wvalid ? Ip[(size_t)hh * WW] : 0.f;
            const float jv = wvalid ? Jp[(size_t)hh * WW] : 0.f;
            S0 += iv; S1 += jv; S2 += iv * iv; S3 += jv * jv; S4 += iv * jv;
        }
    }

    for (int h = h0; h < h0 + HCH; h++) {
        // --- W-sum via warp shuffles (9-tap, zero-padded by construction) ---
        #define WSUM(dst, src)                                                \
        {                                                                     \
            float a = (src);                                                  \
            a += __shfl_down_sync(0xFFFFFFFFu, (src), 1);                     \
            a += __shfl_down_sync(0xFFFFFFFFu, (src), 2);                     \
            a += __shfl_down_sync(0xFFFFFFFFu, (src), 3);                     \
            a += __shfl_down_sync(0xFFFFFFFFu, (src), 4);                     \
            a += __shfl_up_sync(0xFFFFFFFFu, (src), 1);                       \
            a += __shfl_up_sync(0xFFFFFFFFu, (src), 2);                       \
            a += __shfl_up_sync(0xFFFFFFFFu, (src), 3);                       \
            a += __shfl_up_sync(0xFFFFFFFFu, (src), 4);                       \
            dst = a;                                                          \
        }
        float o0, o1, o2, o3, o4;
        WSUM(o0, S0) WSUM(o1, S1) WSUM(o2, S2) WSUM(o3, S3) WSUM(o4, S4)
        #undef WSUM

        if (emit) {
            const size_t obase = pbase + (size_t)h * WW + wout;
            g_buf[0 * (size_t)NVOX + obase] = o0;
            g_buf[1 * (size_t)NVOX + obase] = o1;
            g_buf[2 * (size_t)NVOX + obase] = o2;
            g_buf[3 * (size_t)NVOX + obase] = o3;
            g_buf[4 * (size_t)NVOX + obase] = o4;
        }

        // --- slide H window: add row h+5, subtract row h-4 ---
        if (h != h0 + HCH - 1) {
            const int ha = h + 1 + RAD;
            if (ha < HH) {
                const float iv = wvalid ? Ip[(size_t)ha * WW] : 0.f;
                const float jv = wvalid ? Jp[(size_t)ha * WW] : 0.f;
                S0 += iv; S1 += jv; S2 += iv * iv; S3 += jv * jv; S4 += iv * jv;
            }
            const int hs = h - RAD;
            if (hs >= 0) {
                const float iv = wvalid ? Ip[(size_t)hs * WW] : 0.f;
                const float jv = wvalid ? Jp[(size_t)hs * WW] : 0.f;
                S0 -= iv; S1 -= jv; S2 -= iv * iv; S3 -= jv * jv; S4 -= iv * jv;
            }
        }
    }
}

// ---------------------------------------------------------------------------
// Kernel 2: sliding-sum along D (float4) + fused NCC + block reduction.
// ---------------------------------------------------------------------------
__global__ void __launch_bounds__(NTH2) pass_d_kernel() {
    const int tid = threadIdx.x;
    const int w4 = tid % W4;
    const int hs = tid / W4;           // 0..HB-1
    const int bx = blockIdx.x;
    const int chunk = bx / (BATCH * (HH / HB));
    const int rem = bx % (BATCH * (HH / HB));
    const int b = rem / (HH / HB);
    const int ht = rem % (HH / HB);
    const int h = ht * HB + hs;
    const int d0 = chunk * CDCHUNK;

    const float4* __restrict__ in = (const float4*)g_buf;
    const size_t base = (size_t)b * DD * PLANE4 + (size_t)h * W4 + w4;

    float4 s[NCH];
    #pragma unroll
    for (int c = 0; c < NCH; c++) {
        float4 a = make_float4(0.f, 0.f, 0.f, 0.f);
        #pragma unroll
        for (int dd = d0 - RAD; dd <= d0 + RAD; dd++) {
            if (dd >= 0 && dd < DD) {
                const float4 v = in[(size_t)c * NVOX4 + base + (size_t)dd * PLANE4];
                a.x += v.x; a.y += v.y; a.z += v.z; a.w += v.w;
            }
        }
        s[c] = a;
    }

    float4 cc4 = make_float4(0.f, 0.f, 0.f, 0.f);
    for (int d = d0; d < d0 + CDCHUNK; d++) {
        #define CC_LANE(L)                                                        \
        {                                                                         \
            const float Is = s[0].L, Js = s[1].L, I2 = s[2].L,                    \
                        J2 = s[3].L, IJ = s[4].L;                                 \
            const float cross = IJ - Is * Js * INV_WIN;                           \
            const float Iv = I2 - Is * Is * INV_WIN;                              \
            const float Jv = J2 - Js * Js * INV_WIN;                              \
            cc4.L += (cross * cross) / (Iv * Jv + 1e-5f);                         \
        }
        CC_LANE(x) CC_LANE(y) CC_LANE(z) CC_LANE(w)
        #undef CC_LANE

        if (d != d0 + CDCHUNK - 1) {
            const int add = d + 1 + RAD;
            const int sub = d - RAD;
            #pragma unroll
            for (int c = 0; c < NCH; c++) {
                if (add < DD) {
                    const float4 v = in[(size_t)c * NVOX4 + base + (size_t)add * PLANE4];
                    s[c].x += v.x; s[c].y += v.y; s[c].z += v.z; s[c].w += v.w;
                }
                if (sub >= 0) {
                    const float4 v = in[(size_t)c * NVOX4 + base + (size_t)sub * PLANE4];
                    s[c].x -= v.x; s[c].y -= v.y; s[c].z -= v.z; s[c].w -= v.w;
                }
            }
        }
    }

    float cc_sum = ((cc4.x + cc4.y) + (cc4.z + cc4.w));

    // deterministic reduction: warp shuffle (fixed order), then warp sums
    #pragma unroll
    for (int off = 16; off > 0; off >>= 1)
        cc_sum += __shfl_down_sync(0xFFFFFFFFu, cc_sum, off);

    __shared__ float warp_sums[NTH2 / 32];
    const int lane = tid & 31, warp = tid >> 5;
    if (lane == 0) warp_sums[warp] = cc_sum;
    __syncthreads();
    if (tid == 0) {
        float t = 0.f;
        #pragma unroll
        for (int i = 0; i < NTH2 / 32; i++) t += warp_sums[i];
        g_partial[blockIdx.x] = t;
    }
}

// ---------------------------------------------------------------------------
// Final deterministic reduction of block partials -> scalar out
// ---------------------------------------------------------------------------
__global__ void finalize_kernel(float* __restrict__ out) {
    __shared__ float red[256];
    float a = 0.f;
    for (int i = threadIdx.x; i < GRID2; i += 256) a += g_partial[i];
    red[threadIdx.x] = a;
    __syncthreads();
    #pragma unroll
    for (int off = 128; off > 0; off >>= 1) {
        if (threadIdx.x < off) red[threadIdx.x] += red[threadIdx.x + off];
        __syncthreads();
    }
    if (threadIdx.x == 0) out[0] = -red[0] / (float)NVOX;
}

// ---------------------------------------------------------------------------
extern "C" void kernel_launch(void* const* d_in, const int* in_sizes, int n_in,
                              void* d_out, int out_size) {
    const float* y_true = (const float*)d_in[0];
    const float* y_pred = (const float*)d_in[1];
    float* out = (float*)d_out;

    pass_wh_kernel<<<GRID1, NTH1>>>(y_true, y_pred);
    pass_d_kernel<<<GRID2, NTH2>>>();
    finalize_kernel<<<1, 256>>>(out);
}

// round 13
// speedup vs baseline: 2.1294x; 1.1339x over previous
#include <cuda_runtime.h>

// Problem constants
#define BATCH 2
#define DD 160
#define HH 160
#define WW 160
#define PLANE (HH * WW)               // 25600
#define NVOX (BATCH * DD * HH * WW)   // 8,192,000
#define NCH 5
#define RAD 4
#define INV_WIN (1.0f / 729.0f)

// ---- Kernel 1 (fused W+H, prefix-shuffle stencil, zero smem) ----
#define TEAMW 7                        // warps per row: 7*24 = 168 >= 160 outputs
#define NTH1 (TEAMW * 32)              // 224 threads
#define HCH 20                         // h rows per block
#define NCHH (HH / HCH)                // 8
#define GRID1 (BATCH * DD * NCHH)      // 2560 blocks

// ---- Kernel 2 (D + cc) ----
#define W4 (WW / 4)                    // 40 float4 per row
#define PLANE4 (HH * W4)               // 6400
#define NVOX4 (NVOX / 4)
#define CDCHUNK 16
#define NCHUNK (DD / CDCHUNK)          // 10
#define HB 8                           // h rows per block
#define NTH2 (W4 * HB)                 // 320 threads
#define GRID2 (NCHUNK * BATCH * (HH / HB))  // 400 blocks

// Scratch (allocation-free: __device__ globals)
__device__ float g_buf[(size_t)NCH * NVOX];   // W+H summed, 5 channels
__device__ float g_partial[GRID2];

// ---------------------------------------------------------------------------
// Kernel 1: fused products + H-running-window (registers) + W-sum via warp
// prefix-sum difference (7 shuffles per channel instead of 8-tap gather).
// ---------------------------------------------------------------------------
__global__ void __launch_bounds__(NTH1) pass_wh_kernel(const float* __restrict__ I,
                                                       const float* __restrict__ J) {
    const int tid = threadIdx.x;
    const int warp = tid >> 5;
    const int lane = tid & 31;

    const int bx = blockIdx.x;
    const int plane = bx / NCHH;       // b*DD + d
    const int hc = bx % NCHH;
    const int h0 = hc * HCH;

    const int w = warp * 24 + lane - 4;            // load column (may be OOB)
    const bool wvalid = (w >= 0 && w < WW);
    const int wc = min(max(w, 0), WW - 1);         // safe address
    const size_t pbase = (size_t)plane * PLANE;
    const float* __restrict__ Ip = I + pbase + wc;
    const float* __restrict__ Jp = J + pbase + wc;

    const bool emit = (lane >= 4) && (lane < 28) && (w < WW);

    // H running sums of the 5 products
    float S0 = 0.f, S1 = 0.f, S2 = 0.f, S3 = 0.f, S4 = 0.f;

    // init window for output h0: rows [h0-4, h0+4] (h0+4 <= 144 < HH always)
    #pragma unroll
    for (int k = -RAD; k <= RAD; k++) {
        const int hh = h0 + k;
        if (hh >= 0) {
            const float iv = wvalid ? Ip[(size_t)hh * WW] : 0.f;
            const float jv = wvalid ? Jp[(size_t)hh * WW] : 0.f;
            S0 += iv; S1 += jv; S2 += iv * iv; S3 += jv * jv; S4 += iv * jv;
        }
    }

    for (int h = h0; h < h0 + HCH; h++) {
        // --- 9-tap W-sum via inclusive prefix + difference (7 shuffles) ---
        // out[lane] = P[lane+4] - P[lane-5], P = prefix of S across lanes.
        #define WSUM(dst, src)                                                \
        {                                                                     \
            float p = (src);                                                  \
            float t;                                                          \
            t = __shfl_up_sync(0xFFFFFFFFu, p, 1);  if (lane >= 1)  p += t;   \
            t = __shfl_up_sync(0xFFFFFFFFu, p, 2);  if (lane >= 2)  p += t;   \
            t = __shfl_up_sync(0xFFFFFFFFu, p, 4);  if (lane >= 4)  p += t;   \
            t = __shfl_up_sync(0xFFFFFFFFu, p, 8);  if (lane >= 8)  p += t;   \
            t = __shfl_up_sync(0xFFFFFFFFu, p, 16); if (lane >= 16) p += t;   \
            const float hi = __shfl_down_sync(0xFFFFFFFFu, p, 4);             \
            const float lo = __shfl_up_sync(0xFFFFFFFFu, p, 5);               \
            dst = hi - ((lane >= 5) ? lo : 0.f);                              \
        }
        float o0, o1, o2, o3, o4;
        WSUM(o0, S0) WSUM(o1, S1) WSUM(o2, S2) WSUM(o3, S3) WSUM(o4, S4)
        #undef WSUM

        if (emit) {
            const size_t obase = pbase + (size_t)h * WW + w;
            g_buf[0 * (size_t)NVOX + obase] = o0;
            g_buf[1 * (size_t)NVOX + obase] = o1;
            g_buf[2 * (size_t)NVOX + obase] = o2;
            g_buf[3 * (size_t)NVOX + obase] = o3;
            g_buf[4 * (size_t)NVOX + obase] = o4;
        }

        // --- slide H window: add row h+5, subtract row h-4 ---
        if (h != h0 + HCH - 1) {
            const int ha = h + 1 + RAD;
            if (ha < HH) {
                const float iv = wvalid ? Ip[(size_t)ha * WW] : 0.f;
                const float jv = wvalid ? Jp[(size_t)ha * WW] : 0.f;
                S0 += iv; S1 += jv; S2 += iv * iv; S3 += jv * jv; S4 += iv * jv;
            }
            const int hs = h - RAD;
            if (hs >= 0) {
                const float iv = wvalid ? Ip[(size_t)hs * WW] : 0.f;
                const float jv = wvalid ? Jp[(size_t)hs * WW] : 0.f;
                S0 -= iv; S1 -= jv; S2 -= iv * iv; S3 -= jv * jv; S4 -= iv * jv;
            }
        }
    }
}

// ---------------------------------------------------------------------------
// Kernel 2: sliding-sum along D (float4) + fused NCC + block reduction.
// Interior chunks take a branch-free unrolled fast path.
// ---------------------------------------------------------------------------
__device__ __forceinline__ float4 f4add(float4 a, const float4 v) {
    a.x += v.x; a.y += v.y; a.z += v.z; a.w += v.w; return a;
}
__device__ __forceinline__ float4 f4sub(float4 a, const float4 v) {
    a.x -= v.x; a.y -= v.y; a.z -= v.z; a.w -= v.w; return a;
}

__global__ void __launch_bounds__(NTH2) pass_d_kernel() {
    const int tid = threadIdx.x;
    const int w4 = tid % W4;
    const int hs = tid / W4;           // 0..HB-1
    const int bx = blockIdx.x;
    const int chunk = bx / (BATCH * (HH / HB));
    const int rem = bx % (BATCH * (HH / HB));
    const int b = rem / (HH / HB);
    const int ht = rem % (HH / HB);
    const int h = ht * HB + hs;
    const int d0 = chunk * CDCHUNK;

    const float4* __restrict__ in = (const float4*)g_buf;
    const size_t base = (size_t)b * DD * PLANE4 + (size_t)h * W4 + w4;

    float4 s[NCH];
    #pragma unroll
    for (int c = 0; c < NCH; c++) {
        float4 a = make_float4(0.f, 0.f, 0.f, 0.f);
        #pragma unroll
        for (int dd = d0 - RAD; dd <= d0 + RAD; dd++) {
            if (dd >= 0)   // upper bound d0+4 <= 148 < DD always
                a = f4add(a, in[(size_t)c * NVOX4 + base + (size_t)dd * PLANE4]);
        }
        s[c] = a;
    }

    float4 cc4 = make_float4(0.f, 0.f, 0.f, 0.f);

    #define CC_STEP()                                                         \
    {                                                                         \
        _Pragma("unroll")                                                     \
        for (int L = 0; L < 4; L++) {                                         \
            const float Is = (&s[0].x)[L], Js = (&s[1].x)[L],                 \
                        I2 = (&s[2].x)[L], J2 = (&s[3].x)[L],                 \
                        IJ = (&s[4].x)[L];                                    \
            const float cross = IJ - Is * Js * INV_WIN;                       \
            const float Iv = I2 - Is * Is * INV_WIN;                          \
            const float Jv = J2 - Js * Js * INV_WIN;                          \
            (&cc4.x)[L] += (cross * cross) / (Iv * Jv + 1e-5f);               \
        }                                                                     \
    }

    const bool fast = (d0 != 0) && (d0 != DD - CDCHUNK);
    if (fast) {
        // guard-free: sub = d-4 >= d0-4 >= 12 > 0; add = d+5 <= d0+20 <= 148 < DD
        #pragma unroll 4
        for (int d = d0; d < d0 + CDCHUNK - 1; d++) {
            CC_STEP();
            const int add = d + 1 + RAD;
            const int sub = d - RAD;
            #pragma unroll
            for (int c = 0; c < NCH; c++) {
                s[c] = f4add(s[c], in[(size_t)c * NVOX4 + base + (size_t)add * PLANE4]);
                s[c] = f4sub(s[c], in[(size_t)c * NVOX4 + base + (size_t)sub * PLANE4]);
            }
        }
        CC_STEP();
    } else {
        for (int d = d0; d < d0 + CDCHUNK - 1; d++) {
            CC_STEP();
            const int add = d + 1 + RAD;
            const int sub = d - RAD;
            #pragma unroll
            for (int c = 0; c < NCH; c++) {
                if (add < DD)
                    s[c] = f4add(s[c], in[(size_t)c * NVOX4 + base + (size_t)add * PLANE4]);
                if (sub >= 0)
                    s[c] = f4sub(s[c], in[(size_t)c * NVOX4 + base + (size_t)sub * PLANE4]);
            }
        }
        CC_STEP();
    }
    #undef CC_STEP

    float cc_sum = ((cc4.x + cc4.y) + (cc4.z + cc4.w));

    // deterministic reduction: warp shuffle (fixed order), then warp sums
    #pragma unroll
    for (int off = 16; off > 0; off >>= 1)
        cc_sum += __shfl_down_sync(0xFFFFFFFFu, cc_sum, off);

    __shared__ float warp_sums[NTH2 / 32];
    const int lane = tid & 31, warp = tid >> 5;
    if (lane == 0) warp_sums[warp] = cc_sum;
    __syncthreads();
    if (tid == 0) {
        float t = 0.f;
        #pragma unroll
        for (int i = 0; i < NTH2 / 32; i++) t += warp_sums[i];
        g_partial[blockIdx.x] = t;
    }
}

// ---------------------------------------------------------------------------
// Final deterministic reduction of block partials -> scalar out
// ---------------------------------------------------------------------------
__global__ void finalize_kernel(float* __restrict__ out) {
    __shared__ float red[256];
    float a = 0.f;
    for (int i = threadIdx.x; i < GRID2; i += 256) a += g_partial[i];
    red[threadIdx.x] = a;
    __syncthreads();
    #pragma unroll
    for (int off = 128; off > 0; off >>= 1) {
        if (threadIdx.x < off) red[threadIdx.x] += red[threadIdx.x + off];
        __syncthreads();
    }
    if (threadIdx.x == 0) out[0] = -red[0] / (float)NVOX;
}

// ---------------------------------------------------------------------------
extern "C" void kernel_launch(void* const* d_in, const int* in_sizes, int n_in,
                              void* d_out, int out_size) {
    const float* y_true = (const float*)d_in[0];
    const float* y_pred = (const float*)d_in[1];
    float* out = (float*)d_out;

    pass_wh_kernel<<<GRID1, NTH1>>>(y_true, y_pred);
    pass_d_kernel<<<GRID2, NTH2>>>();
    finalize_kernel<<<1, 256>>>(out);
}